// round 7
// baseline (speedup 1.0000x reference)
#include <cuda_runtime.h>

#define DD 64
#define NMAX 100000
#define EMAX 1200000

// Scratch (allocation-free rule: __device__ globals). 16B-aligned for float4 access.
__device__ __align__(16) float  g_deg[NMAX];      // edge-weight in-degree (no self-loop)
__device__ __align__(16) float  g_dis[NMAX];      // rsqrt(1 + deg)
__device__ __align__(16) int    g_cnt[NMAX];
__device__ __align__(16) int    g_row[NMAX + 1];
__device__ __align__(16) int    g_cur[NMAX];
__device__ __align__(16) float2 g_pair[EMAX];     // (src as int bits, w*dis[src]), bucketed by dst
__device__ __align__(16) float  g_hs [NMAX * DD]; // UNSCALED h = X@W
__device__ __align__(16) float  g_x1 [NMAX * DD]; // layer-1 output

// ---------------------------------------------------------------------------
// FUSED: blocks [0, nb_g) compute h1 = X@W1 (no dis dependency);
//        blocks [nb_g, ...) count in-degree + weighted degree.
__global__ __launch_bounds__(256) void fused_gemm1_count_kernel(
    const float* __restrict__ X, const float* __restrict__ W,
    const int* __restrict__ ei, const float* __restrict__ ew,
    int n, int E, int nb_g)
{
    __shared__ float sW[DD * DD];
    __shared__ float sX[DD * DD];

    int t = threadIdx.x;

    if (blockIdx.x >= nb_g) {
        // ---- count role ----
        int e = (blockIdx.x - nb_g) * blockDim.x + t;
        if (e < E) {
            int d = ei[E + e];
            atomicAdd(&g_cnt[d], 1);
            atomicAdd(&g_deg[d], ew[e]);
        }
        return;
    }

    // ---- gemm role: one block = 64 rows, 4x4 register tiles ----
    int row0 = blockIdx.x * 64;

    {   // W (4096 floats) coalesced as float4
        float4* sW4 = (float4*)sW;
        const float4* W4 = (const float4*)W;
        #pragma unroll
        for (int i = 0; i < 4; i++) sW4[t + i * 256] = W4[t + i * 256];
    }
    {   // X tile, zero-pad OOB rows
        float4* sX4 = (float4*)sX;
        const float4* X4 = (const float4*)X;
        if (row0 + 64 <= n) {
            #pragma unroll
            for (int i = 0; i < 4; i++) sX4[t + i * 256] = X4[(size_t)row0 * 16 + t + i * 256];
        } else {
            #pragma unroll
            for (int i = 0; i < 4; i++) {
                int idx = t + i * 256;
                int r = idx >> 4;
                float4 v = make_float4(0.f, 0.f, 0.f, 0.f);
                if (row0 + r < n) v = X4[(size_t)row0 * 16 + idx];
                sX4[idx] = v;
            }
        }
    }
    __syncthreads();

    int rg = (t >> 4) * 4;
    int c0 = (t & 15) * 4;

    float a[4][4];
    #pragma unroll
    for (int i = 0; i < 4; i++)
        #pragma unroll
        for (int j = 0; j < 4; j++) a[i][j] = 0.f;

    #pragma unroll 16
    for (int k = 0; k < 64; k++) {
        float4 wv = *(const float4*)(sW + k * 64 + c0);
        #pragma unroll
        for (int i = 0; i < 4; i++) {
            float xv = sX[(rg + i) * 64 + k];
            a[i][0] = fmaf(xv, wv.x, a[i][0]);
            a[i][1] = fmaf(xv, wv.y, a[i][1]);
            a[i][2] = fmaf(xv, wv.z, a[i][2]);
            a[i][3] = fmaf(xv, wv.w, a[i][3]);
        }
    }

    float4* hp = (float4*)g_hs;
    #pragma unroll
    for (int i = 0; i < 4; i++) {
        int r = row0 + rg + i;
        if (r < n)
            hp[(size_t)r * 16 + (c0 >> 2)] =
                make_float4(a[i][0], a[i][1], a[i][2], a[i][3]);   // UNSCALED
    }
}

// ---------------------------------------------------------------------------
// Plain GEMM for layer 2: h2 = x1 @ W2 (unscaled).
__global__ __launch_bounds__(256) void gemm_kernel(
    const float* __restrict__ W, int n)
{
    __shared__ float sW[DD * DD];
    __shared__ float sX[DD * DD];
    const float* X = (const float*)g_x1;

    int t = threadIdx.x;
    int row0 = blockIdx.x * 64;

    {
        float4* sW4 = (float4*)sW;
        const float4* W4 = (const float4*)W;
        #pragma unroll
        for (int i = 0; i < 4; i++) sW4[t + i * 256] = W4[t + i * 256];
    }
    {
        float4* sX4 = (float4*)sX;
        const float4* X4 = (const float4*)X;
        if (row0 + 64 <= n) {
            #pragma unroll
            for (int i = 0; i < 4; i++) sX4[t + i * 256] = X4[(size_t)row0 * 16 + t + i * 256];
        } else {
            #pragma unroll
            for (int i = 0; i < 4; i++) {
                int idx = t + i * 256;
                int r = idx >> 4;
                float4 v = make_float4(0.f, 0.f, 0.f, 0.f);
                if (row0 + r < n) v = X4[(size_t)row0 * 16 + idx];
                sX4[idx] = v;
            }
        }
    }
    __syncthreads();

    int rg = (t >> 4) * 4;
    int c0 = (t & 15) * 4;

    float a[4][4];
    #pragma unroll
    for (int i = 0; i < 4; i++)
        #pragma unroll
        for (int j = 0; j < 4; j++) a[i][j] = 0.f;

    #pragma unroll 16
    for (int k = 0; k < 64; k++) {
        float4 wv = *(const float4*)(sW + k * 64 + c0);
        #pragma unroll
        for (int i = 0; i < 4; i++) {
            float xv = sX[(rg + i) * 64 + k];
            a[i][0] = fmaf(xv, wv.x, a[i][0]);
            a[i][1] = fmaf(xv, wv.y, a[i][1]);
            a[i][2] = fmaf(xv, wv.z, a[i][2]);
            a[i][3] = fmaf(xv, wv.w, a[i][3]);
        }
    }

    float4* hp = (float4*)g_hs;
    #pragma unroll
    for (int i = 0; i < 4; i++) {
        int r = row0 + rg + i;
        if (r < n)
            hp[(size_t)r * 16 + (c0 >> 2)] =
                make_float4(a[i][0], a[i][1], a[i][2], a[i][3]);
    }
}

// ---------------------------------------------------------------------------
// single-block exclusive scan of g_cnt -> g_row, g_cur; dis = rsqrt(1 + deg)
__global__ __launch_bounds__(1024) void scan_dis_kernel(int n) {
    __shared__ int ssum[1024];
    int t = threadIdx.x;
    int chunk = (n + 1023) >> 10;
    int beg = t * chunk;
    int end = min(n, beg + chunk);
    int s = 0;
    for (int i = beg; i < end; i++) s += g_cnt[i];
    ssum[t] = s;
    __syncthreads();
    if (t == 0) {
        int acc = 0;
        for (int i = 0; i < 1024; i++) { int v = ssum[i]; ssum[i] = acc; acc += v; }
        g_row[n] = acc;
    }
    __syncthreads();
    int acc = ssum[t];
    for (int i = beg; i < end; i++) {
        int c = g_cnt[i];
        g_row[i] = acc;
        g_cur[i] = acc;
        acc += c;
        g_dis[i] = rsqrtf(1.0f + g_deg[i]);
    }
}

// bucket edges by dst, folding dis[src] into the weight: pair = (s, w*dis[s])
__global__ void fill_kernel(const int* __restrict__ ei,
                            const float* __restrict__ ew, int E) {
    int e = blockIdx.x * blockDim.x + threadIdx.x;
    if (e < E) {
        int s = ei[e];
        int d = ei[E + e];
        int p = atomicAdd(&g_cur[d], 1);
        g_pair[p] = make_float2(__int_as_float(s), ew[e] * g_dis[s]);
    }
}

// ---------------------------------------------------------------------------
// Gather-aggregate: 16 threads per node, thread q owns one float4 column chunk.
//   acc = dis[d]*h[d]  (self-loop);  acc += wp_e * h[src_e]   (wp = w*dis[s])
//   r = relu(dis[d]*acc + b)
//   mode 0: x1 = r          mode 1: out = 0.5*(x1 + r)
__global__ __launch_bounds__(256) void gather_kernel(
    const float* __restrict__ b, float* __restrict__ out, int n, int mode)
{
    int gid = blockIdx.x * blockDim.x + threadIdx.x;
    int d = gid >> 4;
    if (d >= n) return;
    int q = gid & 15;

    const float4* __restrict__ hs4 = (const float4*)g_hs;
    size_t oi = (size_t)d * 16 + q;

    float ds = g_dis[d];
    float4 h0 = hs4[oi];
    float4 acc = make_float4(ds * h0.x, ds * h0.y, ds * h0.z, ds * h0.w);

    int beg = g_row[d];
    int end = g_row[d + 1];

    int i = beg;
    for (; i + 2 <= end; i += 2) {
        float2 p0 = g_pair[i];
        float2 p1 = g_pair[i + 1];
        float4 v0 = hs4[(size_t)__float_as_int(p0.x) * 16 + q];
        float4 v1 = hs4[(size_t)__float_as_int(p1.x) * 16 + q];
        acc.x = fmaf(p0.y, v0.x, acc.x);
        acc.y = fmaf(p0.y, v0.y, acc.y);
        acc.z = fmaf(p0.y, v0.z, acc.z);
        acc.w = fmaf(p0.y, v0.w, acc.w);
        acc.x = fmaf(p1.y, v1.x, acc.x);
        acc.y = fmaf(p1.y, v1.y, acc.y);
        acc.z = fmaf(p1.y, v1.z, acc.z);
        acc.w = fmaf(p1.y, v1.w, acc.w);
    }
    if (i < end) {
        float2 p0 = g_pair[i];
        float4 v0 = hs4[(size_t)__float_as_int(p0.x) * 16 + q];
        acc.x = fmaf(p0.y, v0.x, acc.x);
        acc.y = fmaf(p0.y, v0.y, acc.y);
        acc.z = fmaf(p0.y, v0.z, acc.z);
        acc.w = fmaf(p0.y, v0.w, acc.w);
    }

    int c = q << 2;
    float4 r;
    r.x = fmaxf(fmaf(ds, acc.x, b[c + 0]), 0.f);
    r.y = fmaxf(fmaf(ds, acc.y, b[c + 1]), 0.f);
    r.z = fmaxf(fmaf(ds, acc.z, b[c + 2]), 0.f);
    r.w = fmaxf(fmaf(ds, acc.w, b[c + 3]), 0.f);

    if (mode == 0) {
        ((float4*)g_x1)[oi] = r;
    } else {
        float4 x1v = ((const float4*)g_x1)[oi];
        r.x = 0.5f * (x1v.x + r.x);
        r.y = 0.5f * (x1v.y + r.y);
        r.z = 0.5f * (x1v.z + r.z);
        r.w = 0.5f * (x1v.w + r.w);
        ((float4*)out)[oi] = r;
    }
}

// ---------------------------------------------------------------------------
extern "C" void kernel_launch(void* const* d_in, const int* in_sizes, int n_in,
                              void* d_out, int out_size) {
    const float* x  = (const float*)d_in[0];
    const int*   ei = (const int*)d_in[1];      // int32 (JAX default x64-disabled)
    const float* ew = (const float*)d_in[2];
    const float* W1 = (const float*)d_in[3];
    const float* b1 = (const float*)d_in[4];
    const float* W2 = (const float*)d_in[5];
    const float* b2 = (const float*)d_in[6];
    float* out = (float*)d_out;

    int n = in_sizes[0] / DD;      // 100000
    int E = in_sizes[2];           // 1200000

    int nb_e   = (E + 255) / 256;
    int nb_gat = (int)(((long long)n * 16 + 255) / 256);
    int nb_g   = (n + 63) / 64;

    // Zero cnt/deg via graph memset nodes (deg accumulates edge weights only;
    // the self-loop's +1 moves into dis = rsqrt(1+deg)).
    void* p_cnt = nullptr; void* p_deg = nullptr;
    cudaGetSymbolAddress(&p_cnt, g_cnt);
    cudaGetSymbolAddress(&p_deg, g_deg);
    cudaMemsetAsync(p_cnt, 0, (size_t)n * sizeof(int));
    cudaMemsetAsync(p_deg, 0, (size_t)n * sizeof(float));

    // GEMM1 (h1 = x@W1) co-runs with the degree count in one launch.
    fused_gemm1_count_kernel<<<nb_g + nb_e, 256>>>(x, W1, ei, ew, n, E, nb_g);

    scan_dis_kernel<<<1, 1024>>>(n);
    fill_kernel<<<nb_e, 256>>>(ei, ew, E);           // folds dis[src] into weight

    gather_kernel<<<nb_gat, 256>>>(b1, out, n, 0);   // writes g_x1
    gemm_kernel<<<nb_g, 256>>>(W2, n);               // h2 = x1@W2
    gather_kernel<<<nb_gat, 256>>>(b2, out, n, 1);   // out = 0.5*(x1+x2)
}

// round 10
// speedup vs baseline: 2.1494x; 2.1494x over previous
#include <cuda_runtime.h>
#include <cuda_fp16.h>
#include <cstring>

#define DD 64
#define NMAX 100000
#define EMAX 1200000

// Portable bit-casts (avoid toolchain-specific half2<->uint intrinsic names)
__device__ __forceinline__ unsigned h2_to_u32(__half2 h) {
    unsigned u; memcpy(&u, &h, 4); return u;
}
__device__ __forceinline__ __half2 u32_to_h2(unsigned u) {
    __half2 h; memcpy(&h, &u, 4); return h;
}

// Scratch (allocation-free rule: __device__ globals). 16B-aligned for vector access.
__device__ __align__(16) float  g_deg[NMAX];
__device__ __align__(16) float  g_dis[NMAX];
__device__ __align__(16) int    g_cnt[NMAX];
__device__ __align__(16) int    g_row[NMAX + 1];
__device__ __align__(16) int    g_cur[NMAX];
__device__ __align__(16) float2 g_pair[EMAX];       // (src as int bits, weight), bucketed by dst
__device__ __align__(16) __half g_hs [NMAX * DD];   // fp16: dis[i] * (X@W)[i]  (halves gather traffic)
__device__ __align__(16) float  g_x1 [NMAX * DD];   // layer-1 output (fp32)

// ---------------------------------------------------------------------------
// init: cnt = 0, deg = 1 (self-loop weight)
__global__ void init_kernel(int n) {
    int i = blockIdx.x * blockDim.x + threadIdx.x;
    if (i < n) { g_cnt[i] = 0; g_deg[i] = 1.0f; }
}

// count in-degree + weighted degree.  edge_index is INT32: src = ei[e], dst = ei[E+e].
__global__ void count_kernel(const int* __restrict__ ei,
                             const float* __restrict__ ew, int E) {
    int e = blockIdx.x * blockDim.x + threadIdx.x;
    if (e < E) {
        int d = ei[E + e];
        atomicAdd(&g_cnt[d], 1);
        atomicAdd(&g_deg[d], ew[e]);
    }
}

// single-block exclusive scan of g_cnt -> g_row, g_cur; g_row[n] = E
__global__ __launch_bounds__(1024) void scan_kernel(int n) {
    __shared__ int ssum[1024];
    int t = threadIdx.x;
    int chunk = (n + 1023) >> 10;
    int beg = t * chunk;
    int end = min(n, beg + chunk);
    int s = 0;
    for (int i = beg; i < end; i++) s += g_cnt[i];
    ssum[t] = s;
    __syncthreads();
    if (t == 0) {
        int acc = 0;
        for (int i = 0; i < 1024; i++) { int v = ssum[i]; ssum[i] = acc; acc += v; }
        g_row[n] = acc;
    }
    __syncthreads();
    int acc = ssum[t];
    for (int i = beg; i < end; i++) {
        int c = g_cnt[i];
        g_row[i] = acc;
        g_cur[i] = acc;
        acc += c;
    }
}

// dis = rsqrt(deg)   (deg >= 1 always)
__global__ void dis_kernel(int n) {
    int i = blockIdx.x * blockDim.x + threadIdx.x;
    if (i < n) g_dis[i] = rsqrtf(g_deg[i]);
}

// bucket edges by dst: g_pair[slot] = (src, w)
__global__ void fill_kernel(const int* __restrict__ ei,
                            const float* __restrict__ ew, int E) {
    int e = blockIdx.x * blockDim.x + threadIdx.x;
    if (e < E) {
        int s = ei[e];
        int d = ei[E + e];
        int p = atomicAdd(&g_cur[d], 1);
        g_pair[p] = make_float2(__int_as_float(s), ew[e]);
    }
}

// ---------------------------------------------------------------------------
// GEMM: hs = fp16( dis[row] * (X @ W) ).  One block = 64 rows, 256 threads,
// 4x4 register tiles.  EXACT R6 mainloop (scalar sX loads — no reg blowup).
__global__ __launch_bounds__(256) void gemm_hs_kernel(
    const float* __restrict__ Xin, const float* __restrict__ W, int n, int src_sel)
{
    __shared__ float sW[DD * DD];
    __shared__ float sX[DD * DD];

    const float* X = src_sel ? (const float*)g_x1 : Xin;

    int t = threadIdx.x;
    int row0 = blockIdx.x * 64;

    {   // W (4096 floats) coalesced as float4
        float4* sW4 = (float4*)sW;
        const float4* W4 = (const float4*)W;
        #pragma unroll
        for (int i = 0; i < 4; i++) sW4[t + i * 256] = W4[t + i * 256];
    }
    {   // X tile, zero-pad OOB rows
        float4* sX4 = (float4*)sX;
        const float4* X4 = (const float4*)X;
        if (row0 + 64 <= n) {
            #pragma unroll
            for (int i = 0; i < 4; i++) sX4[t + i * 256] = X4[(size_t)row0 * 16 + t + i * 256];
        } else {
            #pragma unroll
            for (int i = 0; i < 4; i++) {
                int idx = t + i * 256;
                int r = idx >> 4;
                float4 v = make_float4(0.f, 0.f, 0.f, 0.f);
                if (row0 + r < n) v = X4[(size_t)row0 * 16 + idx];
                sX4[idx] = v;
            }
        }
    }
    __syncthreads();

    int rg = (t >> 4) * 4;
    int c0 = (t & 15) * 4;

    float a[4][4];
    #pragma unroll
    for (int i = 0; i < 4; i++)
        #pragma unroll
        for (int j = 0; j < 4; j++) a[i][j] = 0.f;

    #pragma unroll 16
    for (int k = 0; k < 64; k++) {
        float4 wv = *(const float4*)(sW + k * 64 + c0);
        #pragma unroll
        for (int i = 0; i < 4; i++) {
            float xv = sX[(rg + i) * 64 + k];
            a[i][0] = fmaf(xv, wv.x, a[i][0]);
            a[i][1] = fmaf(xv, wv.y, a[i][1]);
            a[i][2] = fmaf(xv, wv.z, a[i][2]);
            a[i][3] = fmaf(xv, wv.w, a[i][3]);
        }
    }

    // Epilogue: scale by dis, convert to fp16, store 4 halves (8B) per thread-row.
    uint2* hp = (uint2*)g_hs;                       // row stride = 64*2B / 8B = 16
    #pragma unroll
    for (int i = 0; i < 4; i++) {
        int r = row0 + rg + i;
        if (r < n) {
            float ds = g_dis[r];
            __half2 h01 = __floats2half2_rn(a[i][0] * ds, a[i][1] * ds);
            __half2 h23 = __floats2half2_rn(a[i][2] * ds, a[i][3] * ds);
            hp[(size_t)r * 16 + (c0 >> 2)] = make_uint2(h2_to_u32(h01), h2_to_u32(h23));
        }
    }
}

// ---------------------------------------------------------------------------
// Gather-aggregate: 16 threads per node, thread q owns 4 fp16 columns (8B).
//   acc = hs[d] (self-loop); acc += w_e * hs[src_e]; r = relu(dis[d]*acc + b)
//   mode 0: x1 = r (fp32)    mode 1: out = 0.5*(x1 + r)
// Edge loop unrolled x2: two independent 8B loads in flight per lane.
__global__ __launch_bounds__(256) void gather_kernel(
    const float* __restrict__ b, float* __restrict__ out, int n, int mode)
{
    int gid = blockIdx.x * blockDim.x + threadIdx.x;
    int d = gid >> 4;
    if (d >= n) return;
    int q = gid & 15;

    const uint2* __restrict__ hs2 = (const uint2*)g_hs;   // row stride 16
    size_t oi = (size_t)d * 16 + q;

    uint2 self = hs2[oi];
    float2 s01 = __half22float2(u32_to_h2(self.x));
    float2 s23 = __half22float2(u32_to_h2(self.y));
    float4 acc = make_float4(s01.x, s01.y, s23.x, s23.y);

    int beg = g_row[d];
    int end = g_row[d + 1];

    int i = beg;
    for (; i + 2 <= end; i += 2) {
        float2 p0 = g_pair[i];
        float2 p1 = g_pair[i + 1];
        uint2 r0 = hs2[(size_t)__float_as_int(p0.x) * 16 + q];
        uint2 r1 = hs2[(size_t)__float_as_int(p1.x) * 16 + q];
        float2 a01 = __half22float2(u32_to_h2(r0.x));
        float2 a23 = __half22float2(u32_to_h2(r0.y));
        float2 b01 = __half22float2(u32_to_h2(r1.x));
        float2 b23 = __half22float2(u32_to_h2(r1.y));
        acc.x = fmaf(p0.y, a01.x, acc.x);
        acc.y = fmaf(p0.y, a01.y, acc.y);
        acc.z = fmaf(p0.y, a23.x, acc.z);
        acc.w = fmaf(p0.y, a23.y, acc.w);
        acc.x = fmaf(p1.y, b01.x, acc.x);
        acc.y = fmaf(p1.y, b01.y, acc.y);
        acc.z = fmaf(p1.y, b23.x, acc.z);
        acc.w = fmaf(p1.y, b23.y, acc.w);
    }
    if (i < end) {
        float2 p0 = g_pair[i];
        uint2 r0 = hs2[(size_t)__float_as_int(p0.x) * 16 + q];
        float2 a01 = __half22float2(u32_to_h2(r0.x));
        float2 a23 = __half22float2(u32_to_h2(r0.y));
        acc.x = fmaf(p0.y, a01.x, acc.x);
        acc.y = fmaf(p0.y, a01.y, acc.y);
        acc.z = fmaf(p0.y, a23.x, acc.z);
        acc.w = fmaf(p0.y, a23.y, acc.w);
    }

    float ds = g_dis[d];
    int c = q << 2;
    float4 r;
    r.x = fmaxf(fmaf(ds, acc.x, b[c + 0]), 0.f);
    r.y = fmaxf(fmaf(ds, acc.y, b[c + 1]), 0.f);
    r.z = fmaxf(fmaf(ds, acc.z, b[c + 2]), 0.f);
    r.w = fmaxf(fmaf(ds, acc.w, b[c + 3]), 0.f);

    if (mode == 0) {
        ((float4*)g_x1)[oi] = r;
    } else {
        float4 x1v = ((const float4*)g_x1)[oi];
        r.x = 0.5f * (x1v.x + r.x);
        r.y = 0.5f * (x1v.y + r.y);
        r.z = 0.5f * (x1v.z + r.z);
        r.w = 0.5f * (x1v.w + r.w);
        ((float4*)out)[oi] = r;
    }
}

// ---------------------------------------------------------------------------
extern "C" void kernel_launch(void* const* d_in, const int* in_sizes, int n_in,
                              void* d_out, int out_size) {
    const float* x  = (const float*)d_in[0];
    const int*   ei = (const int*)d_in[1];      // int32 (JAX default x64-disabled)
    const float* ew = (const float*)d_in[2];
    const float* W1 = (const float*)d_in[3];
    const float* b1 = (const float*)d_in[4];
    const float* W2 = (const float*)d_in[5];
    const float* b2 = (const float*)d_in[6];
    float* out = (float*)d_out;

    int n = in_sizes[0] / DD;      // 100000
    int E = in_sizes[2];           // 1200000

    int nb_n   = (n + 255) / 256;
    int nb_e   = (E + 255) / 256;
    int nb_gat = (int)(((long long)n * 16 + 255) / 256);
    int nb_g   = (n + 63) / 64;

    // CSR + degree (shared across both layers) — exact R6 launch order
    init_kernel<<<nb_n, 256>>>(n);
    count_kernel<<<nb_e, 256>>>(ei, ew, E);
    scan_kernel<<<1, 1024>>>(n);
    dis_kernel<<<nb_n, 256>>>(n);
    fill_kernel<<<nb_e, 256>>>(ei, ew, E);

    // Layer 1
    gemm_hs_kernel<<<nb_g, 256>>>(x, W1, n, 0);
    gather_kernel<<<nb_gat, 256>>>(b1, out, n, 0);     // writes g_x1

    // Layer 2
    gemm_hs_kernel<<<nb_g, 256>>>(x, W2, n, 1);        // reads g_x1
    gather_kernel<<<nb_gat, 256>>>(b2, out, n, 1);     // out = 0.5*(x1+x2)
}